// round 4
// baseline (speedup 1.0000x reference)
#include <cuda_runtime.h>

#define N_RAYS    8192
#define N_SAMPLES 256
#define HIDDEN    64
#define WPB       8              // warps (rays) per block
#define SPL       8              // samples per lane (256 / 32)
#define OUT_STRIDE 261           // 3 color + depth + missed + 256 probs

__device__ __forceinline__ float sigmoidf_fast(float x) {
    return 1.0f / (1.0f + __expf(-x));
}

__global__ __launch_bounds__(WPB * 32)
void volume_render_kernel(
    const float* __restrict__ ray_start,   // [N,3]
    const float* __restrict__ ray_dir,     // [N,3]
    const float* __restrict__ depth,       // [N,P]
    const float* __restrict__ dists,       // [N,P]
    const int*   __restrict__ sidx,        // [N,P] int32 (JAX x64 disabled!)
    const float* __restrict__ W1,          // [3,64]
    const float* __restrict__ b1,          // [64]
    const float* __restrict__ wsig,        // [64]
    const float* __restrict__ Wrgb,        // [64,3]
    const float* __restrict__ Wdir,        // [3,3]
    const float* __restrict__ brgb,        // [3]
    float* __restrict__ out)               // [N,261]
{
    __shared__ float4 wv[HIDDEN];               // {wsig, wr, wg, wb} per channel
    __shared__ float2 sdw[WPB][HIDDEN];         // {s_j, d_j} per warp(ray), per channel

    const int tid  = threadIdx.x;
    const int lane = tid & 31;
    const int w    = tid >> 5;
    const int ray  = blockIdx.x * WPB + w;

    // Block-shared per-channel output weights
    if (tid < HIDDEN) {
        wv[tid] = make_float4(wsig[tid], Wrgb[tid*3+0], Wrgb[tid*3+1], Wrgb[tid*3+2]);
    }

    // Per-ray scalars (broadcast loads)
    const float sx = ray_start[ray*3+0], sy = ray_start[ray*3+1], sz = ray_start[ray*3+2];
    const float dx = ray_dir[ray*3+0],   dy = ray_dir[ray*3+1],   dz = ray_dir[ray*3+2];

    // Direction color term: dir @ Wdir + brgb  (per ray, per color)
    const float dir0 = fmaf(dx, Wdir[0], fmaf(dy, Wdir[3], fmaf(dz, Wdir[6], brgb[0])));
    const float dir1 = fmaf(dx, Wdir[1], fmaf(dy, Wdir[4], fmaf(dz, Wdir[7], brgb[1])));
    const float dir2 = fmaf(dx, Wdir[2], fmaf(dy, Wdir[5], fmaf(dz, Wdir[8], brgb[2])));

    // Per-ray channel decomposition: h_j(t) = relu(s_j + t * d_j)
    //   s_j = start . W1[:,j] + b1_j ;  d_j = dir . W1[:,j]
    #pragma unroll
    for (int j = lane; j < HIDDEN; j += 32) {
        float s = fmaf(sx, W1[j], fmaf(sy, W1[HIDDEN + j], fmaf(sz, W1[2*HIDDEN + j], b1[j])));
        float d = fmaf(dx, W1[j], fmaf(dy, W1[HIDDEN + j], dz * W1[2*HIDDEN + j]));
        sdw[w][j] = make_float2(s, d);
    }
    __syncthreads();

    // Each lane owns SPL contiguous samples: [lane*8, lane*8+8)
    const int sbase = ray * N_SAMPLES + lane * SPL;

    float t[SPL];
    {
        const float4* dp = reinterpret_cast<const float4*>(depth + sbase);
        float4 a = dp[0], b = dp[1];
        t[0]=a.x; t[1]=a.y; t[2]=a.z; t[3]=a.w;
        t[4]=b.x; t[5]=b.y; t[6]=b.z; t[7]=b.w;
    }
    float m7[SPL];   // dists * 7 * mask
    {
        const float4* dp = reinterpret_cast<const float4*>(dists + sbase);
        float4 a = dp[0], b = dp[1];
        float dv[SPL] = {a.x,a.y,a.z,a.w,b.x,b.y,b.z,b.w};
        const int4* ip = reinterpret_cast<const int4*>(sidx + sbase);
        int4 i0 = ip[0], i1 = ip[1];
        int iv[SPL] = {i0.x, i0.y, i0.z, i0.w, i1.x, i1.y, i1.z, i1.w};
        #pragma unroll
        for (int k = 0; k < SPL; k++) {
            m7[k] = (iv[k] != -1) ? 7.0f * dv[k] : 0.0f;
        }
    }

    // Accumulators over channels
    float sig[SPL], cr[SPL], cg[SPL], cb[SPL];
    #pragma unroll
    for (int k = 0; k < SPL; k++) { sig[k]=0.f; cr[k]=0.f; cg[k]=0.f; cb[k]=0.f; }

    // Main MLP loop: channel-outer, sample-inner (weights amortized over 8 samples)
    #pragma unroll 4
    for (int j = 0; j < HIDDEN; j++) {
        const float2 sd = sdw[w][j];
        const float4 wt = wv[j];
        #pragma unroll
        for (int k = 0; k < SPL; k++) {
            float h = fmaxf(fmaf(sd.y, t[k], sd.x), 0.0f);
            sig[k] = fmaf(h, wt.x, sig[k]);
            cr[k]  = fmaf(h, wt.y, cr[k]);
            cg[k]  = fmaf(h, wt.z, cg[k]);
            cb[k]  = fmaf(h, wt.w, cb[k]);
        }
    }

    // free energy + local exclusive prefix
    float fe[SPL], excl[SPL];
    float run = 0.0f;
    #pragma unroll
    for (int k = 0; k < SPL; k++) {
        fe[k] = fmaxf(sig[k], 0.0f) * m7[k];
        excl[k] = run;
        run += fe[k];
    }

    // Warp exclusive scan of lane totals
    float incl = run;
    #pragma unroll
    for (int off = 1; off < 32; off <<= 1) {
        float n = __shfl_up_sync(0xffffffffu, incl, off);
        if (lane >= off) incl += n;
    }
    const float offset = incl - run;   // exclusive prefix of this lane's block

    // probs: prob_k = (1 - exp(-fe_k)) * exp(-(offset + excl_k))
    // Use expm1 to avoid cancellation for small fe; accurate expf for transmittance.
    float prob[SPL];
    #pragma unroll
    for (int k = 0; k < SPL; k++) {
        float a = -expm1f(-fe[k]);            // 1 - exp(-fe)
        float b = expf(-(offset + excl[k]));  // transmittance
        prob[k] = a * b;
    }

    // Per-lane weighted accumulation + prob stores
    float dsum = 0.f, psum = 0.f, ar = 0.f, ag = 0.f, ab = 0.f;
    float* orow = out + (size_t)ray * OUT_STRIDE;
    #pragma unroll
    for (int k = 0; k < SPL; k++) {
        const float p = prob[k];
        dsum = fmaf(t[k], p, dsum);
        psum += p;
        ar = fmaf(sigmoidf_fast(cr[k] + dir0), p, ar);
        ag = fmaf(sigmoidf_fast(cg[k] + dir1), p, ag);
        ab = fmaf(sigmoidf_fast(cb[k] + dir2), p, ab);
        orow[5 + lane * SPL + k] = p;
    }

    // Warp reduction of the 5 scalars
    #pragma unroll
    for (int off = 16; off > 0; off >>= 1) {
        dsum += __shfl_xor_sync(0xffffffffu, dsum, off);
        psum += __shfl_xor_sync(0xffffffffu, psum, off);
        ar   += __shfl_xor_sync(0xffffffffu, ar,   off);
        ag   += __shfl_xor_sync(0xffffffffu, ag,   off);
        ab   += __shfl_xor_sync(0xffffffffu, ab,   off);
    }
    if (lane == 0) {
        orow[0] = ar;
        orow[1] = ag;
        orow[2] = ab;
        orow[3] = dsum;
        orow[4] = 1.0f - psum;
    }
}

extern "C" void kernel_launch(void* const* d_in, const int* in_sizes, int n_in,
                              void* d_out, int out_size) {
    const float* ray_start = (const float*)d_in[0];
    const float* ray_dir   = (const float*)d_in[1];
    const float* depth     = (const float*)d_in[2];
    const float* dists     = (const float*)d_in[3];
    const int*   sidx      = (const int*)d_in[4];     // int32: JAX default x64-disabled
    const float* W1        = (const float*)d_in[5];
    const float* b1        = (const float*)d_in[6];
    const float* wsig      = (const float*)d_in[7];
    const float* Wrgb      = (const float*)d_in[8];
    const float* Wdir      = (const float*)d_in[9];
    const float* brgb      = (const float*)d_in[10];
    float* out = (float*)d_out;

    dim3 grid(N_RAYS / WPB);   // 1024 blocks
    dim3 block(WPB * 32);      // 256 threads = 8 warps = 8 rays
    volume_render_kernel<<<grid, block>>>(ray_start, ray_dir, depth, dists, sidx,
                                          W1, b1, wsig, Wrgb, Wdir, brgb, out);
}

// round 8
// speedup vs baseline: 1.3605x; 1.3605x over previous
#include <cuda_runtime.h>
#include <cstdint>

#define N_RAYS    8192
#define N_SAMPLES 256
#define HIDDEN    64
#define WPB       8              // warps (rays) per block
#define SPL       8              // samples per lane (256 / 32)
#define NPAIR     4              // packed f32x2 pairs per lane
#define OUT_STRIDE 261           // 3 color + depth + missed + 256 probs

typedef unsigned long long u64;

union F2 { u64 v; float2 f; uint2 u; };

__device__ __forceinline__ u64 pack2(float lo, float hi) {
    u64 r; asm("mov.b64 %0, {%1, %2};" : "=l"(r) : "f"(lo), "f"(hi)); return r;
}
__device__ __forceinline__ u64 fma2(u64 a, u64 b, u64 c) {
    u64 d; asm("fma.rn.f32x2 %0, %1, %2, %3;" : "=l"(d) : "l"(a), "l"(b), "l"(c)); return d;
}
__device__ __forceinline__ u64 add2(u64 a, u64 b) {
    u64 d; asm("add.rn.f32x2 %0, %1, %2;" : "=l"(d) : "l"(a), "l"(b)); return d;
}

__device__ __forceinline__ float sigmoidf_fast(float x) {
    return 1.0f / (1.0f + __expf(-x));
}

__global__ __launch_bounds__(WPB * 32)
void volume_render_kernel(
    const float* __restrict__ ray_start,   // [N,3]
    const float* __restrict__ ray_dir,     // [N,3]
    const float* __restrict__ depth,       // [N,P]
    const float* __restrict__ dists,       // [N,P]
    const int*   __restrict__ sidx,        // [N,P] int32
    const float* __restrict__ W1,          // [3,64]
    const float* __restrict__ b1,          // [64]
    const float* __restrict__ wsig,        // [64]
    const float* __restrict__ Wrgb,        // [64,3]
    const float* __restrict__ Wdir,        // [3,3]
    const float* __restrict__ brgb,        // [3]
    float* __restrict__ out)               // [N,261]
{
    // Broadcast-packed weights, pre-halved for the (h+|h|)*(w/2) relu trick.
    __shared__ alignas(16) ulonglong2 wpA[HIDDEN];          // {wsig/2, wr/2} as {x,x},{y,y}
    __shared__ alignas(16) ulonglong2 wpB[HIDDEN];          // {wg/2,  wb/2}
    __shared__ alignas(16) ulonglong2 sdp[WPB][HIDDEN];     // {s,s},{d,d} per ray per channel

    const int tid  = threadIdx.x;
    const int lane = tid & 31;
    const int w    = tid >> 5;
    const int ray  = blockIdx.x * WPB + w;

    if (tid < HIDDEN) {
        float ws = 0.5f * wsig[tid];
        float wr = 0.5f * Wrgb[tid*3+0];
        float wg = 0.5f * Wrgb[tid*3+1];
        float wb = 0.5f * Wrgb[tid*3+2];
        wpA[tid] = make_ulonglong2(pack2(ws, ws), pack2(wr, wr));
        wpB[tid] = make_ulonglong2(pack2(wg, wg), pack2(wb, wb));
    }

    // Per-ray scalars (broadcast loads)
    const float sx = ray_start[ray*3+0], sy = ray_start[ray*3+1], sz = ray_start[ray*3+2];
    const float dx = ray_dir[ray*3+0],   dy = ray_dir[ray*3+1],   dz = ray_dir[ray*3+2];

    // Direction color term: dir @ Wdir + brgb
    const float dir0 = fmaf(dx, Wdir[0], fmaf(dy, Wdir[3], fmaf(dz, Wdir[6], brgb[0])));
    const float dir1 = fmaf(dx, Wdir[1], fmaf(dy, Wdir[4], fmaf(dz, Wdir[7], brgb[1])));
    const float dir2 = fmaf(dx, Wdir[2], fmaf(dy, Wdir[5], fmaf(dz, Wdir[8], brgb[2])));

    // Per-ray channel decomposition: h_j(t) = relu(s_j + t * d_j)
    #pragma unroll
    for (int j = lane; j < HIDDEN; j += 32) {
        float s = fmaf(sx, W1[j], fmaf(sy, W1[HIDDEN + j], fmaf(sz, W1[2*HIDDEN + j], b1[j])));
        float d = fmaf(dx, W1[j], fmaf(dy, W1[HIDDEN + j], dz * W1[2*HIDDEN + j]));
        sdp[w][j] = make_ulonglong2(pack2(s, s), pack2(d, d));
    }
    __syncthreads();

    // Each lane owns SPL contiguous samples: [lane*8, lane*8+8)
    const int sbase = ray * N_SAMPLES + lane * SPL;

    float t[SPL];
    u64 t2[NPAIR];
    {
        const float4* dp = reinterpret_cast<const float4*>(depth + sbase);
        float4 a = dp[0], b = dp[1];
        t[0]=a.x; t[1]=a.y; t[2]=a.z; t[3]=a.w;
        t[4]=b.x; t[5]=b.y; t[6]=b.z; t[7]=b.w;
        t2[0]=pack2(a.x,a.y); t2[1]=pack2(a.z,a.w);
        t2[2]=pack2(b.x,b.y); t2[3]=pack2(b.z,b.w);
    }
    float m7[SPL];   // dists * 7 * mask
    {
        const float4* dp = reinterpret_cast<const float4*>(dists + sbase);
        float4 a = dp[0], b = dp[1];
        float dv[SPL] = {a.x,a.y,a.z,a.w,b.x,b.y,b.z,b.w};
        const int4* ip = reinterpret_cast<const int4*>(sidx + sbase);
        int4 i0 = ip[0], i1 = ip[1];
        int iv[SPL] = {i0.x, i0.y, i0.z, i0.w, i1.x, i1.y, i1.z, i1.w};
        #pragma unroll
        for (int k = 0; k < SPL; k++) {
            m7[k] = (iv[k] != -1) ? 7.0f * dv[k] : 0.0f;
        }
    }

    // Packed accumulators
    u64 sig2[NPAIR], cr2[NPAIR], cg2[NPAIR], cb2[NPAIR];
    #pragma unroll
    for (int p = 0; p < NPAIR; p++) { sig2[p]=0ull; cr2[p]=0ull; cg2[p]=0ull; cb2[p]=0ull; }

    // Main MLP loop, packed f32x2: per pair
    //   h2   = s + t*d                       (1 fma2)
    //   hs2  = h2 + |h2| = 2*relu(h)         (2 LOP3 + 1 add2)
    //   acc += hs2 * (w/2)                   (4 fma2)
    #pragma unroll 8
    for (int j = 0; j < HIDDEN; j++) {
        const ulonglong2 sd = sdp[w][j];       // LDS.128 broadcast
        const ulonglong2 wA = wpA[j];          // LDS.128 broadcast
        const ulonglong2 wB = wpB[j];          // LDS.128 broadcast
        const u64 ss = sd.x, dd = sd.y;
        #pragma unroll
        for (int p = 0; p < NPAIR; p++) {
            u64 h  = fma2(dd, t2[p], ss);
            u64 ha = h & 0x7FFFFFFF7FFFFFFFULL;   // |.| per half (2x LOP3, alu pipe)
            u64 hs = add2(h, ha);                 // 2*relu(h), exact
            sig2[p] = fma2(hs, wA.x, sig2[p]);
            cr2[p]  = fma2(hs, wA.y, cr2[p]);
            cg2[p]  = fma2(hs, wB.x, cg2[p]);
            cb2[p]  = fma2(hs, wB.y, cb2[p]);
        }
    }

    // Unpack accumulators (register-pair aliasing; no math)
    float sig[SPL], cr[SPL], cg[SPL], cb[SPL];
    #pragma unroll
    for (int p = 0; p < NPAIR; p++) {
        F2 a; a.v = sig2[p]; sig[2*p]=a.f.x; sig[2*p+1]=a.f.y;
        F2 b; b.v = cr2[p];  cr[2*p]=b.f.x;  cr[2*p+1]=b.f.y;
        F2 c; c.v = cg2[p];  cg[2*p]=c.f.x;  cg[2*p+1]=c.f.y;
        F2 d; d.v = cb2[p];  cb[2*p]=d.f.x;  cb[2*p+1]=d.f.y;
    }

    // free energy + local exclusive prefix
    float fe[SPL], excl[SPL];
    float run = 0.0f;
    #pragma unroll
    for (int k = 0; k < SPL; k++) {
        fe[k] = fmaxf(sig[k], 0.0f) * m7[k];
        excl[k] = run;
        run += fe[k];
    }

    // Warp exclusive scan of lane totals
    float incl = run;
    #pragma unroll
    for (int off = 1; off < 32; off <<= 1) {
        float n = __shfl_up_sync(0xffffffffu, incl, off);
        if (lane >= off) incl += n;
    }
    const float offset = incl - run;   // exclusive prefix of this lane's block

    // probs: prob_k = (1 - exp(-fe_k)) * exp(-(offset + excl_k))
    float prob[SPL];
    #pragma unroll
    for (int k = 0; k < SPL; k++) {
        float a = -expm1f(-fe[k]);
        float b = expf(-(offset + excl[k]));
        prob[k] = a * b;
    }

    // Per-lane weighted accumulation + prob stores
    float dsum = 0.f, psum = 0.f, ar = 0.f, ag = 0.f, ab = 0.f;
    float* orow = out + (size_t)ray * OUT_STRIDE;
    #pragma unroll
    for (int k = 0; k < SPL; k++) {
        const float p = prob[k];
        dsum = fmaf(t[k], p, dsum);
        psum += p;
        ar = fmaf(sigmoidf_fast(cr[k] + dir0), p, ar);
        ag = fmaf(sigmoidf_fast(cg[k] + dir1), p, ag);
        ab = fmaf(sigmoidf_fast(cb[k] + dir2), p, ab);
        orow[5 + lane * SPL + k] = p;
    }

    // Warp reduction of the 5 scalars
    #pragma unroll
    for (int off = 16; off > 0; off >>= 1) {
        dsum += __shfl_xor_sync(0xffffffffu, dsum, off);
        psum += __shfl_xor_sync(0xffffffffu, psum, off);
        ar   += __shfl_xor_sync(0xffffffffu, ar,   off);
        ag   += __shfl_xor_sync(0xffffffffu, ag,   off);
        ab   += __shfl_xor_sync(0xffffffffu, ab,   off);
    }
    if (lane == 0) {
        orow[0] = ar;
        orow[1] = ag;
        orow[2] = ab;
        orow[3] = dsum;
        orow[4] = 1.0f - psum;
    }
}

extern "C" void kernel_launch(void* const* d_in, const int* in_sizes, int n_in,
                              void* d_out, int out_size) {
    const float* ray_start = (const float*)d_in[0];
    const float* ray_dir   = (const float*)d_in[1];
    const float* depth     = (const float*)d_in[2];
    const float* dists     = (const float*)d_in[3];
    const int*   sidx      = (const int*)d_in[4];
    const float* W1        = (const float*)d_in[5];
    const float* b1        = (const float*)d_in[6];
    const float* wsig      = (const float*)d_in[7];
    const float* Wrgb      = (const float*)d_in[8];
    const float* Wdir      = (const float*)d_in[9];
    const float* brgb      = (const float*)d_in[10];
    float* out = (float*)d_out;

    dim3 grid(N_RAYS / WPB);   // 1024 blocks
    dim3 block(WPB * 32);      // 256 threads = 8 warps = 8 rays
    volume_render_kernel<<<grid, block>>>(ray_start, ray_dir, depth, dists, sidx,
                                          W1, b1, wsig, Wrgb, Wdir, brgb, out);
}